// round 11
// baseline (speedup 1.0000x reference)
#include <cuda_runtime.h>
#include <cuda_bf16.h>
#include <cstdint>

// Problem constants
#define DIM        64
#define HW         4096
#define KCODES     512
#define PIXPB      128
#define NBLOCKS    1024
#define THREADS    256
#define QOFF       131072
#define LOFF       8519680
#define NELEM_Q    8388608.0

// GEMM geometry: K' = 192 (bf16 2-term split: xh*wh | xm*wh | xh*wm)
#define KP         192
#define WSTRIDE    200            // bf16 per row (100 words) -> conflict-free LDS
#define CH_CODES   128
#define NCHUNK     4
#define NKSTEP     12             // 192/16
#define TWIN       5e-5f
#define A_BYTES    (PIXPB*WSTRIDE*2)     // 51200
#define B_BYTES    (CH_CODES*WSTRIDE*2)  // 51200

__device__ float g_part[NBLOCKS];
__device__ float g_wsq[KCODES];
__device__ __align__(16) __nv_bfloat16 g_B[KCODES * WSTRIDE];

#define FINF __int_as_float(0x7f800000)

__device__ __forceinline__ void mma16816(float& d0, float& d1, float& d2, float& d3,
                                         uint32_t a0, uint32_t a1, uint32_t a2, uint32_t a3,
                                         uint32_t b0, uint32_t b1) {
    asm volatile(
        "mma.sync.aligned.m16n8k16.row.col.f32.bf16.bf16.f32 "
        "{%0,%1,%2,%3}, {%4,%5,%6,%7}, {%8,%9}, {%0,%1,%2,%3};"
        : "+f"(d0), "+f"(d1), "+f"(d2), "+f"(d3)
        : "r"(a0), "r"(a1), "r"(a2), "r"(a3), "r"(b0), "r"(b1));
}

__device__ __forceinline__ void updMM(float& m1, int& i1, float& m2, float s, int k) {
    if (s < m1) { m2 = m1; m1 = s; i1 = k; }
    else if (s < m2) m2 = s;
}
__device__ __forceinline__ void mergeMM(float& m1, int& i1, float& m2,
                                        float om1, int oi1, float om2) {
    if (om1 < m1 || (om1 == m1 && oi1 < i1)) { m2 = fminf(m1, om2); m1 = om1; i1 = oi1; }
    else { m2 = fminf(m2, om1); }
}

// ---------------------------------------------------------------------------
// prep: W' split image (cols 0-63 wh, 64-127 wh, 128-191 wm) + exact wsq
// ---------------------------------------------------------------------------
__global__ void vq_prep(const float* __restrict__ wt) {
    int gid = blockIdx.x * 256 + threadIdx.x;   // 128*256 = 32768
    for (int e = gid; e < KCODES * KP; e += 32768) {
        int k = e / KP, q = e - k * KP;
        int blk = q >> 6, d = q & 63;
        float w = wt[k * DIM + d];
        __nv_bfloat16 h = __float2bfloat16(w);
        __nv_bfloat16 v = (blk <= 1) ? h
                        : __float2bfloat16(__fsub_rn(w, __bfloat162float(h)));
        g_B[k * WSTRIDE + q] = v;
    }
    if (gid < KCODES) {
        const float* w = wt + gid * DIM;
        float c = 0.0f;
        #pragma unroll 8
        for (int d = 0; d < DIM; ++d)
            c = __fadd_rn(c, __fmul_rn(w[d], w[d]));
        g_wsq[gid] = c;
    }
}

// ---------------------------------------------------------------------------
// main: bf16-split mma.sync distance GEMM + exact-rechecked argmin + outputs
// warps: wm = wid&3 (pixels 32wm..+31, 2 m16 tiles), wn = wid>>2 (codes 64wn..+63)
// ---------------------------------------------------------------------------
__global__ __launch_bounds__(THREADS, 2)
void vq_main(const float* __restrict__ in, const float* __restrict__ wt,
             float* __restrict__ out) {
    extern __shared__ unsigned char smraw[];
    __nv_bfloat16* As = reinterpret_cast<__nv_bfloat16*>(smraw);            // [128][200]
    __nv_bfloat16* Bs = reinterpret_cast<__nv_bfloat16*>(smraw + A_BYTES);  // [128][200]
    float* Xs = reinterpret_cast<float*>(smraw);             // reuse A: [64][128] fp32
    float* sc = reinterpret_cast<float*>(smraw + A_BYTES);   // reuse B: [8][512]

    __shared__ float cs[PIXPB];
    __shared__ int   idxs[PIXPB];
    __shared__ float wsqs[KCODES];
    __shared__ float red_m1[256], red_m2[256];
    __shared__ int   red_i1[256];
    __shared__ int   rare_cnt;
    __shared__ int   rare_px[PIXPB];
    __shared__ float warp_part[8];

    const int tid  = threadIdx.x;
    const int wid  = tid >> 5;
    const int lane = tid & 31;
    const int g    = lane >> 2;
    const int tg   = lane & 3;
    const int wm   = wid & 3;
    const int wn   = wid >> 2;
    const int pbase = blockIdx.x * PIXPB;
    const int bb   = pbase >> 12;
    const int hw   = pbase & 4095;
    const float* inb = in + (size_t)bb * (DIM * HW) + hw;

    if (tid == 0) rare_cnt = 0;
    for (int i = tid; i < KCODES; i += THREADS) wsqs[i] = g_wsq[i];

    // A' fill (px = tid < 128) + exact ||x||^2 sequential chain
    if (tid < PIXPB) {
        const float* xp = inb + tid;
        __nv_bfloat16* row = As + tid * WSTRIDE;
        float c = 0.0f;
        #pragma unroll 4
        for (int d = 0; d < DIM; ++d) {
            float x = xp[d * HW];
            c = __fadd_rn(c, __fmul_rn(x, x));
            __nv_bfloat16 h = __float2bfloat16(x);
            __nv_bfloat16 m = __float2bfloat16(__fsub_rn(x, __bfloat162float(h)));
            row[d]       = h;
            row[64 + d]  = m;
            row[128 + d] = h;
        }
        cs[tid] = c;
    }
    __syncthreads();

    // cs for this thread's 4 pixel rows
    float csr[4] = {cs[32 * wm + g], cs[32 * wm + 8 + g],
                    cs[32 * wm + 16 + g], cs[32 * wm + 24 + g]};

    float m1[4], m2[4]; int i1[4];
    #pragma unroll
    for (int r = 0; r < 4; ++r) { m1[r] = FINF; m2[r] = FINF; i1[r] = 0; }

    const uint32_t aw0 = (uint32_t)((32 * wm + g) * 100 + tg);
    const uint32_t bw0 = (uint32_t)((64 * wn + g) * 100 + tg);
    const uint32_t* Aw = reinterpret_cast<const uint32_t*>(As);
    const uint32_t* Bw = reinterpret_cast<const uint32_t*>(Bs);

    for (int ch = 0; ch < NCHUNK; ++ch) {
        // copy W' chunk (51200 B) from L2-resident image
        {
            const float4* src = reinterpret_cast<const float4*>(g_B + ch * CH_CODES * WSTRIDE);
            float4* dst = reinterpret_cast<float4*>(Bs);
            #pragma unroll
            for (int r = 0; r < 13; ++r) {
                int i = tid + r * THREADS;
                if (i < B_BYTES / 16) dst[i] = src[i];
            }
        }
        __syncthreads();

        float acc[2][8][4];
        #pragma unroll
        for (int r = 0; r < 2; ++r)
            #pragma unroll
            for (int c = 0; c < 8; ++c)
                #pragma unroll
                for (int e = 0; e < 4; ++e) acc[r][c][e] = 0.0f;

        #pragma unroll
        for (int ks = 0; ks < NKSTEP; ++ks) {
            const uint32_t ab = aw0 + ks * 8;
            uint32_t a00 = Aw[ab],        a01 = Aw[ab + 800];
            uint32_t a02 = Aw[ab + 4],    a03 = Aw[ab + 804];
            uint32_t a10 = Aw[ab + 1600], a11 = Aw[ab + 2400];
            uint32_t a12 = Aw[ab + 1604], a13 = Aw[ab + 2404];
            #pragma unroll
            for (int c = 0; c < 8; ++c) {
                const uint32_t bbase = bw0 + c * 800 + ks * 8;
                uint32_t b0 = Bw[bbase], b1 = Bw[bbase + 4];
                mma16816(acc[0][c][0], acc[0][c][1], acc[0][c][2], acc[0][c][3],
                         a00, a01, a02, a03, b0, b1);
                mma16816(acc[1][c][0], acc[1][c][1], acc[1][c][2], acc[1][c][3],
                         a10, a11, a12, a13, b0, b1);
            }
        }

        // scores + per-row (m1,i1,m2); ascending k within thread
        #pragma unroll
        for (int c = 0; c < 8; ++c) {
            int kb = ch * CH_CODES + 64 * wn + 8 * c + 2 * tg;
            float w0 = wsqs[kb], w1 = wsqs[kb + 1];
            updMM(m1[0], i1[0], m2[0], __fadd_rn(__fmaf_rn(acc[0][c][0], -2.0f, csr[0]), w0), kb);
            updMM(m1[0], i1[0], m2[0], __fadd_rn(__fmaf_rn(acc[0][c][1], -2.0f, csr[0]), w1), kb + 1);
            updMM(m1[1], i1[1], m2[1], __fadd_rn(__fmaf_rn(acc[0][c][2], -2.0f, csr[1]), w0), kb);
            updMM(m1[1], i1[1], m2[1], __fadd_rn(__fmaf_rn(acc[0][c][3], -2.0f, csr[1]), w1), kb + 1);
            updMM(m1[2], i1[2], m2[2], __fadd_rn(__fmaf_rn(acc[1][c][0], -2.0f, csr[2]), w0), kb);
            updMM(m1[2], i1[2], m2[2], __fadd_rn(__fmaf_rn(acc[1][c][1], -2.0f, csr[2]), w1), kb + 1);
            updMM(m1[3], i1[3], m2[3], __fadd_rn(__fmaf_rn(acc[1][c][2], -2.0f, csr[3]), w0), kb);
            updMM(m1[3], i1[3], m2[3], __fadd_rn(__fmaf_rn(acc[1][c][3], -2.0f, csr[3]), w1), kb + 1);
        }
        __syncthreads();   // all warps done with Bs before next copy
    }

    // merge across tg lanes (bfly 1, 2), then write per (row, wn) to smem
    #pragma unroll
    for (int r = 0; r < 4; ++r) {
        #pragma unroll
        for (int mask = 1; mask <= 2; mask <<= 1) {
            float om1 = __shfl_xor_sync(0xffffffffu, m1[r], mask);
            int   oi1 = __shfl_xor_sync(0xffffffffu, i1[r], mask);
            float om2 = __shfl_xor_sync(0xffffffffu, m2[r], mask);
            mergeMM(m1[r], i1[r], m2[r], om1, oi1, om2);
        }
    }
    if (tg == 0) {
        #pragma unroll
        for (int r = 0; r < 4; ++r) {
            int row = 32 * wm + 8 * r + g;
            red_m1[row * 2 + wn] = m1[r];
            red_i1[row * 2 + wn] = i1[r];
            red_m2[row * 2 + wn] = m2[r];
        }
    }
    __syncthreads();

    // final per-pixel decision + rare collection
    if (tid < PIXPB) {
        float M1 = red_m1[tid * 2], M2 = red_m2[tid * 2];
        int   I1 = red_i1[tid * 2];
        mergeMM(M1, I1, M2, red_m1[tid * 2 + 1], red_i1[tid * 2 + 1], red_m2[tid * 2 + 1]);
        idxs[tid] = I1;
        if (M2 - M1 <= TWIN) {
            int s = atomicAdd(&rare_cnt, 1);
            rare_px[s] = tid;
        }
    }
    __syncthreads();

    // reload X fp32 into A region (GEMM done)
    for (int i = tid; i < DIM * PIXPB; i += THREADS) {
        int d = i >> 7, px = i & 127;
        Xs[d * 128 + px] = inb[d * HW + px];
    }
    __syncthreads();

    // rare pixels: cooperative exact fp32 rescoring (bit-identical chain)
    const int nr = rare_cnt;
    for (int base = 0; base < nr; base += 8) {
        int np = min(8, nr - base);
        for (int j = tid; j < np * KCODES; j += THREADS) {
            int pi = j >> 9, k = j & 511;
            int px = rare_px[base + pi];
            const float* w = wt + k * DIM;
            float a = 0.0f;
            #pragma unroll 8
            for (int d = 0; d < DIM; ++d)
                a = __fmaf_rn(Xs[d * 128 + px], w[d], a);
            sc[pi * KCODES + k] = __fadd_rn(__fmaf_rn(a, -2.0f, cs[px]), wsqs[k]);
        }
        __syncthreads();
        if (wid < np) {   // one warp per rare pixel; first-min semantics
            int px = rare_px[base + wid];
            float best = FINF; int bk = 0x7fffffff;
            for (int k = lane; k < KCODES; k += 32) {  // ascending within lane
                float s = sc[wid * KCODES + k];
                if (s < best) { best = s; bk = k; }
            }
            #pragma unroll
            for (int mask = 16; mask >= 1; mask >>= 1) {
                float os = __shfl_xor_sync(0xffffffffu, best, mask);
                int   ok = __shfl_xor_sync(0xffffffffu, bk, mask);
                if (os < best || (os == best && ok < bk)) { best = os; bk = ok; }
            }
            if (lane == 0) idxs[px] = bk;
        }
        __syncthreads();
    }

    if (tid < PIXPB) out[pbase + tid] = (float)idxs[tid];

    // quantized (straight-through rounding) + loss partial
    float* outq = out + QOFF + (size_t)bb * (DIM * HW) + hw;
    {
        const int px = tid & 127;
        const int d0 = tid >> 7;
        const int k = idxs[px];
        const float* w = wt + k * DIM;
        float lsum = 0.0f;
        #pragma unroll 4
        for (int r = 0; r < 32; ++r) {
            int d = d0 + 2 * r;
            float q = w[d];
            float x = Xs[d * 128 + px];
            float df = __fsub_rn(q, x);
            lsum = __fmaf_rn(df, df, lsum);
            outq[d * HW + px] = __fadd_rn(x, df);
        }
        #pragma unroll
        for (int off = 16; off > 0; off >>= 1)
            lsum += __shfl_down_sync(0xffffffffu, lsum, off);
        if (lane == 0) warp_part[wid] = lsum;
    }
    __syncthreads();
    if (tid == 0) {
        float tot = 0.0f;
        #pragma unroll
        for (int w = 0; w < 8; ++w) tot += warp_part[w];
        g_part[blockIdx.x] = tot;
    }
}

// ---------------------------------------------------------------------------
// finalize: loss = m + 0.25*m,  m = mean((q - x)^2)
// ---------------------------------------------------------------------------
__global__ void vq_fin(float* __restrict__ out) {
    __shared__ double red[256];
    const int tid = threadIdx.x;
    double t = 0.0;
    #pragma unroll
    for (int r = 0; r < NBLOCKS / 256; ++r)
        t += (double)g_part[tid + r * 256];
    red[tid] = t;
    __syncthreads();
    for (int off = 128; off > 0; off >>= 1) {
        if (tid < off) red[tid] += red[tid + off];
        __syncthreads();
    }
    if (tid == 0) {
        double m = red[0] / NELEM_Q;
        out[LOFF] = (float)(m + 0.25 * m);
    }
}

extern "C" void kernel_launch(void* const* d_in, const int* in_sizes, int n_in,
                              void* d_out, int out_size) {
    (void)in_sizes; (void)n_in; (void)out_size;
    const float* in = (const float*)d_in[0];
    const float* wt = (const float*)d_in[1];
    float* out = (float*)d_out;

    const int smem = A_BYTES + B_BYTES;   // 102400 B dynamic
    cudaFuncSetAttribute(vq_main, cudaFuncAttributeMaxDynamicSharedMemorySize, smem);

    vq_prep<<<128, 256>>>(wt);
    vq_main<<<NBLOCKS, THREADS, smem>>>(in, wt, out);
    vq_fin<<<1, 256>>>(out);
}